// round 1
// baseline (speedup 1.0000x reference)
#include <cuda_runtime.h>
#include <math.h>

#define N_SAMP 400000
#define XDIMC  128
#define TPB    256
#define NBLK   ((N_SAMP + TPB - 1) / TPB)   /* 1563 */

// ---------------- scratch (static device globals; no runtime allocation) -----
__device__ float g_z[3 * N_SAMP];            // SoA: [z1 | dcos | deuc]
__device__ float g_gamma[4 * N_SAMP];        // SoA per k
__device__ float g_part1[NBLK * 17];         // gamma[4], gamma*z[12], eucsq[1]
__device__ float g_part2[NBLK * 24];         // per-k 6 unique sigma entries
__device__ float g_part3[NBLK];              // energy partial sums
__device__ float g_G[256], g_wb[16], g_bb[1];
__device__ float g_gs[4], g_mu[12], g_loss1[1];
__device__ float g_B[6], g_beta[3], g_alpha[1], g_loss3[1];

// ---------------- deterministic block reduction (blockDim == 256) ------------
template <int V>
__device__ __forceinline__ void block_reduce(float (&vals)[V], float* red, float* out) {
    int lane = threadIdx.x & 31;
    int wid  = threadIdx.x >> 5;
#pragma unroll
    for (int v = 0; v < V; v++) {
        float x = vals[v];
#pragma unroll
        for (int o = 16; o > 0; o >>= 1) x += __shfl_down_sync(0xffffffffu, x, o);
        vals[v] = x;
    }
    if (lane == 0) {
#pragma unroll
        for (int v = 0; v < V; v++) red[wid * V + v] = vals[v];
    }
    __syncthreads();
    if ((int)threadIdx.x < V) {
        float s = 0.f;
#pragma unroll
        for (int w = 0; w < 8; w++) s += red[w * V + threadIdx.x];
        out[threadIdx.x] = s;
    }
}

// ---------------- K0: precompute Gram of dec_w3, wb, bb ----------------------
__global__ void k_prep(const float* __restrict__ dw3, const float* __restrict__ db3) {
    int tid = threadIdx.x;
    if (tid < 256) {
        int j = tid >> 4, k = tid & 15;
        float s = 0.f;
        for (int i = 0; i < 128; i++) s = fmaf(dw3[j * 128 + i], dw3[k * 128 + i], s);
        g_G[tid] = s;
    }
    if (tid < 16) {
        float s = 0.f;
        for (int i = 0; i < 128; i++) s = fmaf(dw3[tid * 128 + i], db3[i], s);
        g_wb[tid] = s;
    }
    if (tid == 0) {
        float s = 0.f;
        for (int i = 0; i < 128; i++) s = fmaf(db3[i], db3[i], s);
        g_bb[0] = s;
    }
}

// ---------------- K1: heavy per-sample pass ----------------------------------
__global__ __launch_bounds__(TPB) void k_passA(
    const float* __restrict__ x1,
    const float* __restrict__ ew1, const float* __restrict__ eb1,
    const float* __restrict__ ew2, const float* __restrict__ eb2,
    const float* __restrict__ ew3, const float* __restrict__ eb3,
    const float* __restrict__ dw1, const float* __restrict__ db1,
    const float* __restrict__ dw2, const float* __restrict__ db2,
    const float* __restrict__ dw3, const float* __restrict__ db3,
    const float* __restrict__ tw1, const float* __restrict__ tb1,
    const float* __restrict__ tw2, const float* __restrict__ tb2)
{
    __shared__ __align__(16) float s_ew1[128 * 16];
    __shared__ __align__(16) float s_dwT[128 * 16];   // dec_w3 transposed: [i][j]
    __shared__ float s_b3[128];
    __shared__ float s_eb1[16], s_ew2[16 * 8], s_eb2[8], s_ew3[8], s_eb3[1];
    __shared__ float s_dw1[8], s_db1[8], s_dw2[8 * 16], s_db2[16];
    __shared__ float s_G[256], s_wb[16], s_bb[1];
    __shared__ float s_tw1[24], s_tb1[8], s_tw2[32], s_tb2[4];
    __shared__ float s_red[8 * 17];

    int tid = threadIdx.x;
    for (int idx = tid; idx < 2048; idx += TPB) s_ew1[idx] = ew1[idx];
    for (int idx = tid; idx < 2048; idx += TPB) {
        // read dw3 linearly (coalesced), scatter transposed into shared
        int j = idx >> 7, i = idx & 127;
        s_dwT[i * 16 + j] = dw3[idx];
    }
    if (tid < 128) s_b3[tid] = db3[tid];
    if (tid < 16)  s_eb1[tid] = eb1[tid];
    if (tid < 128) s_ew2[tid] = ew2[tid];
    if (tid < 8)   s_eb2[tid] = eb2[tid];
    if (tid < 8)   s_ew3[tid] = ew3[tid];
    if (tid == 0)  s_eb3[0]   = eb3[0];
    if (tid < 8)   s_dw1[tid] = dw1[tid];
    if (tid < 8)   s_db1[tid] = db1[tid];
    if (tid < 128) s_dw2[tid] = dw2[tid];
    if (tid < 16)  s_db2[tid] = db2[tid];
    if (tid < 256) s_G[tid]   = g_G[tid];
    if (tid < 16)  s_wb[tid]  = g_wb[tid];
    if (tid == 0)  s_bb[0]    = g_bb[0];
    if (tid < 24)  s_tw1[tid] = tw1[tid];
    if (tid < 8)   s_tb1[tid] = tb1[tid];
    if (tid < 32)  s_tw2[tid] = tw2[tid];
    if (tid < 4)   s_tb2[tid] = tb2[tid];
    __syncthreads();

    int n = blockIdx.x * TPB + tid;
    float r[17];
#pragma unroll
    for (int v = 0; v < 17; v++) r[v] = 0.f;

    if (n < N_SAMP) {
        const float* xrow = x1 + (size_t)n * XDIMC;
        float u[16], vv[16];
#pragma unroll
        for (int j = 0; j < 16; j++) { u[j] = 0.f; vv[j] = 0.f; }
        float s = 0.f, t = 0.f;

#pragma unroll 1
        for (int i0 = 0; i0 < XDIMC; i0 += 8) {
            float4 xa = *reinterpret_cast<const float4*>(xrow + i0);
            float4 xb = *reinterpret_cast<const float4*>(xrow + i0 + 4);
            float xs[8] = { xa.x, xa.y, xa.z, xa.w, xb.x, xb.y, xb.z, xb.w };
#pragma unroll
            for (int c = 0; c < 8; c++) {
                float xv = xs[c];
                int row = i0 + c;
                const float4* wp1 = reinterpret_cast<const float4*>(s_ew1 + row * 16);
                const float4* wp2 = reinterpret_cast<const float4*>(s_dwT + row * 16);
#pragma unroll
                for (int q = 0; q < 4; q++) {
                    float4 wa = wp1[q];
                    float4 wb4 = wp2[q];
                    u[4 * q + 0] = fmaf(xv, wa.x, u[4 * q + 0]);
                    u[4 * q + 1] = fmaf(xv, wa.y, u[4 * q + 1]);
                    u[4 * q + 2] = fmaf(xv, wa.z, u[4 * q + 2]);
                    u[4 * q + 3] = fmaf(xv, wa.w, u[4 * q + 3]);
                    vv[4 * q + 0] = fmaf(xv, wb4.x, vv[4 * q + 0]);
                    vv[4 * q + 1] = fmaf(xv, wb4.y, vv[4 * q + 1]);
                    vv[4 * q + 2] = fmaf(xv, wb4.z, vv[4 * q + 2]);
                    vv[4 * q + 3] = fmaf(xv, wb4.w, vv[4 * q + 3]);
                }
                s = fmaf(xv, xv, s);
                t = fmaf(xv, s_b3[row], t);
            }
        }

        // encoder tail
        float a[16];
#pragma unroll
        for (int j = 0; j < 16; j++) a[j] = tanhf(u[j] + s_eb1[j]);
        float h2[8];
#pragma unroll
        for (int k = 0; k < 8; k++) {
            float acc = s_eb2[k];
#pragma unroll
            for (int j = 0; j < 16; j++) acc = fmaf(a[j], s_ew2[j * 8 + k], acc);
            h2[k] = tanhf(acc);
        }
        float z1a = s_eb3[0];
#pragma unroll
        for (int k = 0; k < 8; k++) z1a = fmaf(h2[k], s_ew3[k], z1a);
        float z1 = tanhf(z1a);

        // decoder (up to h = d2[16]); x2 never materialized
        float d1[8];
#pragma unroll
        for (int k = 0; k < 8; k++) d1[k] = tanhf(fmaf(z1, s_dw1[k], s_db1[k]));
        float d2[16];
#pragma unroll
        for (int j = 0; j < 16; j++) {
            float acc = s_db2[j];
#pragma unroll
            for (int k = 0; k < 8; k++) acc = fmaf(d1[k], s_dw2[k * 16 + j], acc);
            d2[j] = tanhf(acc);
        }

        // distances via Gram trick
        float hv = 0.f, hwb = 0.f, hGh = 0.f;
#pragma unroll
        for (int j = 0; j < 16; j++) {
            hv  = fmaf(d2[j], vv[j], hv);
            hwb = fmaf(d2[j], s_wb[j], hwb);
            float gj = 0.f;
#pragma unroll
            for (int k = 0; k < 16; k++) gj = fmaf(s_G[j * 16 + k], d2[k], gj);
            hGh = fmaf(d2[j], gj, hGh);
        }
        float x1x2  = hv + t;
        float n2    = hGh + 2.f * hwb + s_bb[0];
        float eucsq = s - 2.f * x1x2 + n2;
        float deuc  = sqrtf(fmaxf(eucsq, 0.f));
        float dcos  = x1x2 / sqrtf(s * n2);

        // estimator -> softmax
        float e1[8];
#pragma unroll
        for (int k = 0; k < 8; k++) {
            float acc = s_tb1[k];
            acc = fmaf(z1,   s_tw1[k],      acc);
            acc = fmaf(dcos, s_tw1[8 + k],  acc);
            acc = fmaf(deuc, s_tw1[16 + k], acc);
            e1[k] = tanhf(acc);
        }
        float lg[4];
#pragma unroll
        for (int q = 0; q < 4; q++) {
            float acc = s_tb2[q];
#pragma unroll
            for (int k = 0; k < 8; k++) acc = fmaf(e1[k], s_tw2[k * 4 + q], acc);
            lg[q] = acc;
        }
        float m = fmaxf(fmaxf(lg[0], lg[1]), fmaxf(lg[2], lg[3]));
        float ex0 = expf(lg[0] - m), ex1 = expf(lg[1] - m);
        float ex2 = expf(lg[2] - m), ex3 = expf(lg[3] - m);
        float inv = 1.f / (ex0 + ex1 + ex2 + ex3);
        float gam[4] = { ex0 * inv, ex1 * inv, ex2 * inv, ex3 * inv };

        // stores (SoA, coalesced)
        g_z[n]              = z1;
        g_z[N_SAMP + n]     = dcos;
        g_z[2 * N_SAMP + n] = deuc;
#pragma unroll
        for (int q = 0; q < 4; q++) g_gamma[q * N_SAMP + n] = gam[q];

        // reduction payload
#pragma unroll
        for (int q = 0; q < 4; q++) {
            r[q] = gam[q];
            r[4 + q * 3 + 0] = gam[q] * z1;
            r[4 + q * 3 + 1] = gam[q] * dcos;
            r[4 + q * 3 + 2] = gam[q] * deuc;
        }
        r[16] = eucsq;
    }

    block_reduce<17>(r, s_red, &g_part1[blockIdx.x * 17]);
}

// ---------------- K2: reduce partials -> gamma_sum, mu, loss1 ---------------
__global__ __launch_bounds__(TPB) void k_reduce1() {
    __shared__ float red[8 * 17];
    __shared__ float sfin[17];
    float acc[17];
#pragma unroll
    for (int v = 0; v < 17; v++) acc[v] = 0.f;
    for (int b = threadIdx.x; b < NBLK; b += TPB) {
#pragma unroll
        for (int v = 0; v < 17; v++) acc[v] += g_part1[b * 17 + v];
    }
    block_reduce<17>(acc, red, sfin);
    __syncthreads();
    if (threadIdx.x == 0) {
        for (int k = 0; k < 4; k++) g_gs[k] = sfin[k];
        for (int k = 0; k < 4; k++)
            for (int c = 0; c < 3; c++)
                g_mu[k * 3 + c] = sfin[4 + k * 3 + c] / sfin[k];
        g_loss1[0] = sfin[16] / (float)N_SAMP;
    }
}

// ---------------- K3: centered second moments --------------------------------
__global__ __launch_bounds__(TPB) void k_sigma() {
    __shared__ float red[8 * 24];
    __shared__ float smu[12];
    if (threadIdx.x < 12) smu[threadIdx.x] = g_mu[threadIdx.x];
    __syncthreads();

    int n = blockIdx.x * TPB + threadIdx.x;
    float r[24];
#pragma unroll
    for (int v = 0; v < 24; v++) r[v] = 0.f;
    if (n < N_SAMP) {
        float z0 = g_z[n], z1 = g_z[N_SAMP + n], z2 = g_z[2 * N_SAMP + n];
#pragma unroll
        for (int k = 0; k < 4; k++) {
            float g  = g_gamma[k * N_SAMP + n];
            float d0 = z0 - smu[k * 3 + 0];
            float d1 = z1 - smu[k * 3 + 1];
            float d2 = z2 - smu[k * 3 + 2];
            r[k * 6 + 0] = g * d0 * d0;
            r[k * 6 + 1] = g * d0 * d1;
            r[k * 6 + 2] = g * d0 * d2;
            r[k * 6 + 3] = g * d1 * d1;
            r[k * 6 + 4] = g * d1 * d2;
            r[k * 6 + 5] = g * d2 * d2;
        }
    }
    block_reduce<24>(r, red, &g_part2[blockIdx.x * 24]);
}

// ---------------- K4: sigma -> inv, det, fold into (alpha, beta, B), loss3 ---
__global__ __launch_bounds__(TPB) void k_stats2() {
    __shared__ float red[8 * 24];
    __shared__ float S[24];
    float acc[24];
#pragma unroll
    for (int v = 0; v < 24; v++) acc[v] = 0.f;
    for (int b = threadIdx.x; b < NBLK; b += TPB) {
#pragma unroll
        for (int v = 0; v < 24; v++) acc[v] += g_part2[b * 24 + v];
    }
    block_reduce<24>(acc, red, S);
    __syncthreads();

    if (threadIdx.x == 0) {
        const float LOG_2PI = 1.8378770664093454f; // log(2*pi)
        float B0 = 0.f, B1 = 0.f, B2 = 0.f, B3 = 0.f, B4 = 0.f, B5 = 0.f;
        float be0 = 0.f, be1 = 0.f, be2 = 0.f, alpha = 0.f, l3 = 0.f;
        for (int k = 0; k < 4; k++) {
            float gs = g_gs[k];
            float a = S[k * 6 + 0] / gs, b = S[k * 6 + 1] / gs, c = S[k * 6 + 2] / gs;
            float d = S[k * 6 + 3] / gs, e = S[k * 6 + 4] / gs, f = S[k * 6 + 5] / gs;
            float det = a * (d * f - e * e) - b * (b * f - e * c) + c * (b * e - d * c);
            float id  = 1.f / det;
            float A00 = (d * f - e * e) * id, A01 = (c * e - b * f) * id, A02 = (b * e - c * d) * id;
            float A11 = (a * f - c * c) * id, A12 = (b * c - a * e) * id, A22 = (a * d - b * b) * id;
            float m0 = g_mu[k * 3 + 0], m1 = g_mu[k * 3 + 1], m2 = g_mu[k * 3 + 2];
            float phi = gs / (float)N_SAMP;
            float ck  = logf(phi) - 0.5f * (3.f * LOG_2PI + logf(det));
            float Am0 = A00 * m0 + A01 * m1 + A02 * m2;
            float Am1 = A01 * m0 + A11 * m1 + A12 * m2;
            float Am2 = A02 * m0 + A12 * m1 + A22 * m2;
            float mAm = m0 * Am0 + m1 * Am1 + m2 * Am2;
            B0 += 0.5f * A00; B1 += 0.5f * A01; B2 += 0.5f * A02;
            B3 += 0.5f * A11; B4 += 0.5f * A12; B5 += 0.5f * A22;
            be0 -= Am0; be1 -= Am1; be2 -= Am2;
            alpha += -ck + 0.5f * mAm;
            l3 += 1.f / a + 1.f / d + 1.f / f;
        }
        g_B[0] = B0; g_B[1] = B1; g_B[2] = B2; g_B[3] = B3; g_B[4] = B4; g_B[5] = B5;
        g_beta[0] = be0; g_beta[1] = be1; g_beta[2] = be2;
        g_alpha[0] = alpha;
        g_loss3[0] = 0.0001f * l3;
    }
}

// ---------------- K5: per-sample energy + sum --------------------------------
__global__ __launch_bounds__(TPB) void k_energy(float* __restrict__ out) {
    __shared__ float red[8];
    int n = blockIdx.x * TPB + threadIdx.x;
    float r[1];
    r[0] = 0.f;
    if (n < N_SAMP) {
        float z0 = g_z[n], zc = g_z[N_SAMP + n], ze = g_z[2 * N_SAMP + n];
        float q = g_B[0] * z0 * z0 + g_B[3] * zc * zc + g_B[5] * ze * ze
                + 2.f * (g_B[1] * z0 * zc + g_B[2] * z0 * ze + g_B[4] * zc * ze);
        float en = g_alpha[0] + g_beta[0] * z0 + g_beta[1] * zc + g_beta[2] * ze + q;
        out[n] = en;
        r[0] = en;
    }
    block_reduce<1>(r, red, &g_part3[blockIdx.x]);
}

// ---------------- K6: finalize loss ------------------------------------------
__global__ __launch_bounds__(TPB) void k_final(float* __restrict__ out, int out_size) {
    __shared__ float red[8];
    __shared__ float sfin[1];
    float acc[1];
    acc[0] = 0.f;
    for (int b = threadIdx.x; b < NBLK; b += TPB) acc[0] += g_part3[b];
    block_reduce<1>(acc, red, sfin);
    __syncthreads();
    if (threadIdx.x == 0 && out_size > N_SAMP) {
        float esum = sfin[0];
        out[N_SAMP] = g_loss1[0] + 0.01f * (esum / (float)N_SAMP) + g_loss3[0];
    }
}

// ---------------- launch -----------------------------------------------------
extern "C" void kernel_launch(void* const* d_in, const int* in_sizes, int n_in,
                              void* d_out, int out_size) {
    const float* x1  = (const float*)d_in[0];
    const float* ew1 = (const float*)d_in[1];
    const float* eb1 = (const float*)d_in[2];
    const float* ew2 = (const float*)d_in[3];
    const float* eb2 = (const float*)d_in[4];
    const float* ew3 = (const float*)d_in[5];
    const float* eb3 = (const float*)d_in[6];
    const float* dw1 = (const float*)d_in[7];
    const float* db1 = (const float*)d_in[8];
    const float* dw2 = (const float*)d_in[9];
    const float* db2 = (const float*)d_in[10];
    const float* dw3 = (const float*)d_in[11];
    const float* db3 = (const float*)d_in[12];
    const float* tw1 = (const float*)d_in[13];
    const float* tb1 = (const float*)d_in[14];
    const float* tw2 = (const float*)d_in[15];
    const float* tb2 = (const float*)d_in[16];
    float* out = (float*)d_out;

    k_prep<<<1, 256>>>(dw3, db3);
    k_passA<<<NBLK, TPB>>>(x1, ew1, eb1, ew2, eb2, ew3, eb3,
                           dw1, db1, dw2, db2, dw3, db3,
                           tw1, tb1, tw2, tb2);
    k_reduce1<<<1, TPB>>>();
    k_sigma<<<NBLK, TPB>>>();
    k_stats2<<<1, TPB>>>();
    k_energy<<<NBLK, TPB>>>(out);
    k_final<<<1, TPB>>>(out, out_size);
}